// round 4
// baseline (speedup 1.0000x reference)
#include <cuda_runtime.h>
#include <cuda_bf16.h>
#include <math.h>
#include <stdint.h>

// Problem constants
#define BB   8
#define SS   2048
#define HH   16
#define DHH  64
#define DD   1024            // H*DH
#define MM   (BB*SS)         // 16384

// ---------------- scratch (__device__ globals; allocation-free) -------------
__device__ float g_Q     [BB*SS*DD];   // Q = Q_seq @ WQ        (B,S,D)
__device__ float g_K     [BB*SS*DD];   // K = K_seq @ WK        (B,S,D)
__device__ float g_logits[BB*HH*SS];   // (B,H,S)
__device__ float g_gq    [BB*HH*DHH];  // (B,H,DH) = (B, D)
__device__ float g_gk    [BB*HH*DHH];
__device__ __nv_bfloat16 g_Bhi[DD*DD]; // split+transposed weight Bt[n,k]
__device__ __nv_bfloat16 g_Blo[DD*DD];

// ======================= PTX helpers ========================================
__device__ __forceinline__ uint32_t smem_to_u32(const void* p) {
    uint32_t a;
    asm("{ .reg .u64 t; cvta.to.shared.u64 t, %1; cvt.u32.u64 %0, t; }"
        : "=r"(a) : "l"(p));
    return a;
}
#define LDSM4(r, addr) asm volatile( \
    "ldmatrix.sync.aligned.m8n8.x4.shared.b16 {%0,%1,%2,%3}, [%4];" \
    : "=r"((r)[0]), "=r"((r)[1]), "=r"((r)[2]), "=r"((r)[3]) : "r"(addr))
#define MMA_BF16(d, a, b) asm volatile( \
    "mma.sync.aligned.m16n8k16.row.col.f32.bf16.bf16.f32 " \
    "{%0,%1,%2,%3}, {%4,%5,%6,%7}, {%8,%9}, {%0,%1,%2,%3};" \
    : "+f"((d)[0]), "+f"((d)[1]), "+f"((d)[2]), "+f"((d)[3]) \
    : "r"((a)[0]), "r"((a)[1]), "r"((a)[2]), "r"((a)[3]), \
      "r"((b)[0]), "r"((b)[1]))
__device__ __forceinline__ void cp16(uint32_t dst, const void* src) {
    asm volatile("cp.async.cg.shared.global [%0], [%1], 16;"
                 :: "r"(dst), "l"(src) : "memory");
}
#define CP_COMMIT()  asm volatile("cp.async.commit_group;" ::: "memory")
#define CP_WAIT_1()  asm volatile("cp.async.wait_group 1;" ::: "memory")
#define CP_WAIT_0()  asm volatile("cp.async.wait_group 0;" ::: "memory")

__device__ __forceinline__ uint32_t pack_hi(float a, float b) {
    __nv_bfloat162 t;
    t.x = __float2bfloat16(a);
    t.y = __float2bfloat16(b);
    return *(uint32_t*)&t;
}
__device__ __forceinline__ uint32_t pack_lo(float a, float b) {
    float ra = a - __bfloat162float(__float2bfloat16(a));
    float rb = b - __bfloat162float(__float2bfloat16(b));
    __nv_bfloat162 t;
    t.x = __float2bfloat16(ra);
    t.y = __float2bfloat16(rb);
    return *(uint32_t*)&t;
}

// ======================= HMMA split-bf16 GEMM ===============================
// C[M,N=1024] = A_f32 @ Bt_bf16(hi/lo) (+res), A optionally scaled per (b,k).
// CTA tile 128m x 128n, BK=32, 8 warps, warp tile 64m x 32n, double buffered.
// SMEM stage layout (80B-padded rows => conflict-free ldmatrix):
//   A_hi: [128][80B] @ 0       A_lo @ 10240
//   B_hi: [128][80B] @ 20480   B_lo @ 30720
#define STAGE_B   40960
#define GEMM_SMEM (2 * STAGE_B)
#define KB        32          // 1024 / 32

template<bool SC, bool RES>
__global__ __launch_bounds__(256, 1) void hmma_gemm_kernel(
    const float* __restrict__ A,
    const __nv_bfloat16* __restrict__ Bhi, const __nv_bfloat16* __restrict__ Blo,
    float* __restrict__ C, const float* __restrict__ g,
    const float* __restrict__ res)
{
    extern __shared__ __align__(128) char smem[];
    const uint32_t sb = smem_to_u32(smem);
    const int tid = threadIdx.x;
    const int lane = tid & 31;
    const int wid  = tid >> 5;
    const int warpM = wid >> 2;            // 0..1  (64 rows each)
    const int warpN = wid & 3;             // 0..3  (32 cols each)
    const int colBase = blockIdx.x * 128;
    const int rowBase = blockIdx.y * 128;

    // ---- A load mapping: 4 x 16B fp32 chunks per thread per k-block
    const int am = tid >> 3;               // 0..31 (+32*i)
    const int ac = (tid & 7) * 4;          // k offset (floats)
    const float* aPtr[4];
    uint32_t aOff[4];                      // byte offset within stage
    #pragma unroll
    for (int i = 0; i < 4; i++) {
        const int m = am + 32 * i;
        aPtr[i] = A + (size_t)(rowBase + m) * DD + ac;
        aOff[i] = m * 80 + ac * 2;
    }
    const float* grow = SC ? (g + (size_t)(blockIdx.y >> 4) * DD + ac) : (const float*)0;

    // ---- B cp.async mapping: 2 x 16B chunks per ver per thread per k-block
    const int bn = tid >> 1;                    // 0..127
    const int bco = (tid & 1) * 32;             // byte offset of first chunk
    const size_t bSrc = (size_t)(colBase + bn) * DD + (bco >> 1);
    const uint32_t bDst = bn * 80 + bco;

    // ---- prologue: kb = 0
    float4 rA[4];
    float4 gs;
    #pragma unroll
    for (int i = 0; i < 4; i++) rA[i] = *(const float4*)(aPtr[i]);
    if (SC) gs = *(const float4*)(grow);
    cp16(sb + 20480 + bDst,      Bhi + bSrc);
    cp16(sb + 20480 + bDst + 16, Bhi + bSrc + 8);
    cp16(sb + 30720 + bDst,      Blo + bSrc);
    cp16(sb + 30720 + bDst + 16, Blo + bSrc + 8);
    CP_COMMIT();

    float acc[4][4][4];
    #pragma unroll
    for (int mf = 0; mf < 4; mf++)
        #pragma unroll
        for (int nf = 0; nf < 4; nf++)
            #pragma unroll
            for (int q = 0; q < 4; q++) acc[mf][nf][q] = 0.f;

    const int lrow = lane & 15;
    const int lc16 = (lane >> 4) * 16;

    for (int kb = 0; kb < KB; kb++) {
        const int stOff = (kb & 1) * STAGE_B;
        const uint32_t st = sb + stOff;

        // store A (convert fp32 -> hi/lo bf16) for this kb
        #pragma unroll
        for (int i = 0; i < 4; i++) {
            float4 v = rA[i];
            if (SC) { v.x *= gs.x; v.y *= gs.y; v.z *= gs.z; v.w *= gs.w; }
            uint2 h = make_uint2(pack_hi(v.x, v.y), pack_hi(v.z, v.w));
            uint2 l = make_uint2(pack_lo(v.x, v.y), pack_lo(v.z, v.w));
            *(uint2*)(smem + stOff + aOff[i])         = h;
            *(uint2*)(smem + stOff + aOff[i] + 10240) = l;
        }

        if (kb + 1 < KB) {
            const int ko = (kb + 1) * 32;
            #pragma unroll
            for (int i = 0; i < 4; i++) rA[i] = *(const float4*)(aPtr[i] + ko);
            if (SC) gs = *(const float4*)(grow + ko);
            const uint32_t st2 = sb + ((kb + 1) & 1) * STAGE_B;
            cp16(st2 + 20480 + bDst,      Bhi + bSrc + ko);
            cp16(st2 + 20480 + bDst + 16, Bhi + bSrc + ko + 8);
            cp16(st2 + 30720 + bDst,      Blo + bSrc + ko);
            cp16(st2 + 30720 + bDst + 16, Blo + bSrc + ko + 8);
            CP_COMMIT();
            CP_WAIT_1();
        } else {
            CP_WAIT_0();
        }
        __syncthreads();

        // ---- compute on stage st
        #pragma unroll
        for (int ks = 0; ks < 2; ks++) {
            uint32_t af[2][4][4];   // [ver][mf]
            uint32_t bf[2][4][2];   // [ver][nf]
            #pragma unroll
            for (int ver = 0; ver < 2; ver++) {
                const uint32_t aB = st + ver * 10240 +
                                    (warpM * 64 + lrow) * 80 + lc16 + ks * 32;
                #pragma unroll
                for (int mf = 0; mf < 4; mf++)
                    LDSM4(af[ver][mf], aB + mf * 16 * 80);
                const uint32_t bB = st + 20480 + ver * 10240 +
                                    (warpN * 32 + lrow) * 80 + lc16 + ks * 32;
                #pragma unroll
                for (int np = 0; np < 2; np++) {
                    uint32_t r[4];
                    LDSM4(r, bB + np * 16 * 80);
                    bf[ver][np * 2 + 0][0] = r[0]; bf[ver][np * 2 + 0][1] = r[2];
                    bf[ver][np * 2 + 1][0] = r[1]; bf[ver][np * 2 + 1][1] = r[3];
                }
            }
            #pragma unroll
            for (int mf = 0; mf < 4; mf++)
                #pragma unroll
                for (int nf = 0; nf < 4; nf++) {
                    MMA_BF16(acc[mf][nf], af[0][mf], bf[0][nf]);
                    MMA_BF16(acc[mf][nf], af[0][mf], bf[1][nf]);
                    MMA_BF16(acc[mf][nf], af[1][mf], bf[0][nf]);
                }
        }
        __syncthreads();
    }

    // ---- epilogue
    const int er = lane >> 2;
    const int ec = (lane & 3) * 2;
    #pragma unroll
    for (int mf = 0; mf < 4; mf++) {
        const int row0 = rowBase + warpM * 64 + mf * 16 + er;
        #pragma unroll
        for (int nf = 0; nf < 4; nf++) {
            const int col = colBase + warpN * 32 + nf * 8 + ec;
            float2 v0 = make_float2(acc[mf][nf][0], acc[mf][nf][1]);
            float2 v1 = make_float2(acc[mf][nf][2], acc[mf][nf][3]);
            if (RES) {
                const float2 r0 = *(const float2*)(res + (size_t)row0 * DD + col);
                const float2 r1 = *(const float2*)(res + (size_t)(row0 + 8) * DD + col);
                v0.x += r0.x; v0.y += r0.y; v1.x += r1.x; v1.y += r1.y;
            }
            *(float2*)(C + (size_t)row0 * DD + col) = v0;
            *(float2*)(C + (size_t)(row0 + 8) * DD + col) = v1;
        }
    }
}

// ======================= weight transpose + split ===========================
__global__ __launch_bounds__(256) void wsplit_kernel(
    const float* __restrict__ W, __nv_bfloat16* __restrict__ bhi,
    __nv_bfloat16* __restrict__ blo)
{
    __shared__ float tile[32][33];
    const int tx = threadIdx.x & 31, ty0 = threadIdx.x >> 5;
    const int nbase = blockIdx.x * 32, kbase = blockIdx.y * 32;
    #pragma unroll
    for (int j = 0; j < 4; j++) {
        int r = ty0 + j * 8;
        tile[r][tx] = W[(size_t)(kbase + r) * DD + nbase + tx];
    }
    __syncthreads();
    #pragma unroll
    for (int j = 0; j < 4; j++) {
        int n = nbase + ty0 + j * 8;
        int k = kbase + tx;
        float v = tile[tx][ty0 + j * 8];
        __nv_bfloat16 h = __float2bfloat16(v);
        float r = v - __bfloat162float(h);
        bhi[(size_t)n * DD + k] = h;
        blo[(size_t)n * DD + k] = __float2bfloat16(r);
    }
}

// ======================= middle kernels =====================================
// q logits: logits[b,h,s] = scale * X[m,:]@W[:,h] - (1-mask[m])*1e8
__global__ __launch_bounds__(256) void logits_kernel(
    const float* __restrict__ X, const float* __restrict__ W,
    const float* __restrict__ mask, float* __restrict__ logits)
{
    const int m = blockIdx.x;
    const int b = m >> 11;
    const int s = m & (SS - 1);
    const int tid = threadIdx.x;
    const int h = tid >> 4, g = tid & 15;
    const float* xrow = X + (size_t)m * DD;

    float acc = 0.f;
    #pragma unroll 4
    for (int d = g; d < DD; d += 16)
        acc += xrow[d] * W[d * HH + h];

    __shared__ float red[256];
    red[tid] = acc;
    __syncthreads();
    if (tid < HH) {
        float v = 0.f;
        #pragma unroll
        for (int g2 = 0; g2 < 16; g2++) v += red[tid * 16 + g2];
        logits[((size_t)(b * HH + tid)) * SS + s] =
            v * 0.125f - (1.f - mask[m]) * 1e8f;
    }
}

// fused k logits: row s' of QK_flat = gather of K scaled by gq.
//   h' = s'>>7,  QK_flat[b,s',j*64+dh] = K[b, (s'&127)*16+j, h'*64+dh]*gq[b,h',dh]
__global__ __launch_bounds__(256) void k_logits_kernel(
    const float* __restrict__ K, const float* __restrict__ gq,
    const float* __restrict__ W, const float* __restrict__ mask,
    float* __restrict__ logits)
{
    const int m = blockIdx.x;
    const int b = m >> 11;
    const int s = m & (SS - 1);
    const int hp = s >> 7;
    const int sbase = (s & 127) * 16;
    const int tid = threadIdx.x;

    __shared__ float x[DD];
    __shared__ float red[256];

    const float* gqr = gq + (size_t)(b * HH + hp) * DHH;
    #pragma unroll
    for (int t = 0; t < 4; t++) {
        const int idx = tid + t * 256;
        const int j = idx >> 6, dh = idx & 63;
        x[idx] = K[((size_t)(b * SS + sbase + j)) * DD + hp * DHH + dh] * gqr[dh];
    }
    __syncthreads();

    const int h = tid >> 4, g = tid & 15;
    float acc = 0.f;
    #pragma unroll 4
    for (int d = g; d < DD; d += 16)
        acc += x[d] * W[d * HH + h];

    red[tid] = acc;
    __syncthreads();
    if (tid < HH) {
        float v = 0.f;
        #pragma unroll
        for (int g2 = 0; g2 < 16; g2++) v += red[tid * 16 + g2];
        logits[((size_t)(b * HH + tid)) * SS + s] =
            v * 0.125f - (1.f - mask[m]) * 1e8f;
    }
}

// att = softmax(logits[b,h,:]); gout[b,h,dh] = (gmul?) * sum_s att[s]*src[...]
template<bool GM>
__global__ __launch_bounds__(256) void softmax_wsum_kernel(
    const float* __restrict__ logits, const float* __restrict__ src,
    float* __restrict__ gout, const float* __restrict__ gmul)
{
    const int b = blockIdx.x >> 4, h = blockIdx.x & 15;
    const int tid = threadIdx.x;
    const float* lrow = logits + (size_t)(b * HH + h) * SS;

    __shared__ float att[SS];
    __shared__ float red[256];

    float mx = -3.4e38f;
    for (int s = tid; s < SS; s += 256) mx = fmaxf(mx, lrow[s]);
    red[tid] = mx; __syncthreads();
    for (int off = 128; off > 0; off >>= 1) {
        if (tid < off) red[tid] = fmaxf(red[tid], red[tid + off]);
        __syncthreads();
    }
    mx = red[0];
    __syncthreads();

    float sum = 0.f;
    for (int s = tid; s < SS; s += 256) {
        float e = expf(lrow[s] - mx);
        att[s] = e;
        sum += e;
    }
    red[tid] = sum; __syncthreads();
    for (int off = 128; off > 0; off >>= 1) {
        if (tid < off) red[tid] += red[tid + off];
        __syncthreads();
    }
    const float inv = 1.f / red[0];
    __syncthreads();

    const int dh = tid & 63, j = tid >> 6;
    const float* base = src + (size_t)b * (SS * DD) + h * DHH + dh;
    float acc = 0.f;
    for (int s = j; s < SS; s += 4)
        acc += att[s] * base[(size_t)s * DD];

    red[tid] = acc; __syncthreads();
    if (j == 0) {
        acc = red[dh] + red[64 + dh] + red[128 + dh] + red[192 + dh];
        float r = acc * inv;
        if (GM) r *= gmul[(b * HH + h) * DHH + dh];
        gout[(b * HH + h) * DHH + dh] = r;
    }
}

// ===========================================================================
extern "C" void kernel_launch(void* const* d_in, const int* in_sizes, int n_in,
                              void* d_out, int out_size)
{
    const float* Qseq  = (const float*)d_in[0];
    const float* Kseq  = (const float*)d_in[1];
    const float* Qmask = (const float*)d_in[2];
    const float* Kmask = (const float*)d_in[3];
    const float* WQ    = (const float*)d_in[4];
    const float* WK    = (const float*)d_in[5];
    const float* Wq    = (const float*)d_in[6];
    const float* Wk    = (const float*)d_in[7];
    const float* WP    = (const float*)d_in[8];
    float* out = (float*)d_out;

    float *pQ, *pK, *pL, *pgq, *pgk;
    __nv_bfloat16 *pBhi, *pBlo;
    cudaGetSymbolAddress((void**)&pQ,   g_Q);
    cudaGetSymbolAddress((void**)&pK,   g_K);
    cudaGetSymbolAddress((void**)&pL,   g_logits);
    cudaGetSymbolAddress((void**)&pgq,  g_gq);
    cudaGetSymbolAddress((void**)&pgk,  g_gk);
    cudaGetSymbolAddress((void**)&pBhi, g_Bhi);
    cudaGetSymbolAddress((void**)&pBlo, g_Blo);

    cudaFuncSetAttribute(hmma_gemm_kernel<false, false>,
                         cudaFuncAttributeMaxDynamicSharedMemorySize, GEMM_SMEM);
    cudaFuncSetAttribute(hmma_gemm_kernel<true, true>,
                         cudaFuncAttributeMaxDynamicSharedMemorySize, GEMM_SMEM);

    const dim3 gg(DD / 128, MM / 128);   // (8, 128)
    const dim3 wg(DD / 32, DD / 32);     // (32, 32)

    // 1) Q = Q_seq @ WQ
    wsplit_kernel<<<wg, 256>>>(WQ, pBhi, pBlo);
    hmma_gemm_kernel<false, false><<<gg, 256, GEMM_SMEM>>>(
        Qseq, pBhi, pBlo, pQ, nullptr, nullptr);

    // 2) K = K_seq @ WK
    wsplit_kernel<<<wg, 256>>>(WK, pBhi, pBlo);
    hmma_gemm_kernel<false, false><<<gg, 256, GEMM_SMEM>>>(
        Kseq, pBhi, pBlo, pK, nullptr, nullptr);

    // 3) q logits + softmax + global_q
    logits_kernel<<<MM, 256>>>(pQ, Wq, Qmask, pL);
    softmax_wsum_kernel<false><<<BB * HH, 256>>>(pL, pQ, pgq, nullptr);

    // 4) k logits (fused QK gather) + softmax + global_k (fused gq mul)
    k_logits_kernel<<<MM, 256>>>(pK, pgq, Wk, Kmask, pL);
    softmax_wsum_kernel<true><<<BB * HH, 256>>>(pL, pK, pgk, pgq);

    // 5) out = ((gk ⊙ Q) @ WP) + Q
    wsplit_kernel<<<wg, 256>>>(WP, pBhi, pBlo);
    hmma_gemm_kernel<true, true><<<gg, 256, GEMM_SMEM>>>(
        pQ, pBhi, pBlo, out, pgk, pQ);
}

// round 5
// speedup vs baseline: 1.1084x; 1.1084x over previous
#include <cuda_runtime.h>
#include <cuda_bf16.h>
#include <math.h>
#include <stdint.h>

// Problem constants
#define BB   8
#define SS   2048
#define HH   16
#define DHH  64
#define DD   1024            // H*DH
#define MM   (BB*SS)         // 16384

// ---------------- scratch (__device__ globals; allocation-free) -------------
__device__ float g_Q     [BB*SS*DD];   // Q = Q_seq @ WQ        (B,S,D)
__device__ float g_K     [BB*SS*DD];   // K = K_seq @ WK        (B,S,D)
__device__ float g_logits[BB*HH*SS];   // (B,H,S)
__device__ float g_gq    [BB*HH*DHH];  // (B,H,DH) = (B, D)
__device__ float g_gk    [BB*HH*DHH];
__device__ __nv_bfloat16 g_Bhi[DD*DD]; // split+transposed weight Bt[n,k]
__device__ __nv_bfloat16 g_Blo[DD*DD];

// ======================= PTX helpers ========================================
__device__ __forceinline__ uint32_t smem_to_u32(const void* p) {
    uint32_t a;
    asm("{ .reg .u64 t; cvta.to.shared.u64 t, %1; cvt.u32.u64 %0, t; }"
        : "=r"(a) : "l"(p));
    return a;
}
#define LDSM4(r, addr) asm volatile( \
    "ldmatrix.sync.aligned.m8n8.x4.shared.b16 {%0,%1,%2,%3}, [%4];" \
    : "=r"((r)[0]), "=r"((r)[1]), "=r"((r)[2]), "=r"((r)[3]) : "r"(addr))
#define MMA_BF16(d, a, b) asm volatile( \
    "mma.sync.aligned.m16n8k16.row.col.f32.bf16.bf16.f32 " \
    "{%0,%1,%2,%3}, {%4,%5,%6,%7}, {%8,%9}, {%0,%1,%2,%3};" \
    : "+f"((d)[0]), "+f"((d)[1]), "+f"((d)[2]), "+f"((d)[3]) \
    : "r"((a)[0]), "r"((a)[1]), "r"((a)[2]), "r"((a)[3]), \
      "r"((b)[0]), "r"((b)[1]))
__device__ __forceinline__ void cp16(uint32_t dst, const void* src) {
    asm volatile("cp.async.cg.shared.global [%0], [%1], 16;"
                 :: "r"(dst), "l"(src) : "memory");
}
#define CP_COMMIT()  asm volatile("cp.async.commit_group;" ::: "memory")
#define CP_WAIT_1()  asm volatile("cp.async.wait_group 1;" ::: "memory")
#define CP_WAIT_0()  asm volatile("cp.async.wait_group 0;" ::: "memory")

__device__ __forceinline__ uint32_t pack_hi(float a, float b) {
    __nv_bfloat162 t;
    t.x = __float2bfloat16(a);
    t.y = __float2bfloat16(b);
    return *(uint32_t*)&t;
}
__device__ __forceinline__ uint32_t pack_lo(float a, float b) {
    float ra = a - __bfloat162float(__float2bfloat16(a));
    float rb = b - __bfloat162float(__float2bfloat16(b));
    __nv_bfloat162 t;
    t.x = __float2bfloat16(ra);
    t.y = __float2bfloat16(rb);
    return *(uint32_t*)&t;
}

// ======================= HMMA split-bf16 GEMM ===============================
// C[M,N=1024] = A_f32 @ Bt_bf16(hi/lo) (+res), A optionally scaled per (b,k).
// CTA tile 128m x 128n, BK=32, 8 warps, warp tile 64m x 32n, double buffered,
// 2 CTAs/SM (reg cap 128, smem 80KB/CTA).
// SMEM stage layout (80B-padded rows => conflict-free ldmatrix):
//   A_hi: [128][80B] @ 0       A_lo @ 10240
//   B_hi: [128][80B] @ 20480   B_lo @ 30720
#define STAGE_B   40960
#define GEMM_SMEM (2 * STAGE_B)
#define KB        32          // 1024 / 32

template<bool SC, bool RES>
__global__ __launch_bounds__(256, 2) void hmma_gemm_kernel(
    const float* __restrict__ A,
    const __nv_bfloat16* __restrict__ Bhi, const __nv_bfloat16* __restrict__ Blo,
    float* __restrict__ C, const float* __restrict__ g,
    const float* __restrict__ res)
{
    extern __shared__ __align__(128) char smem[];
    const uint32_t sb = smem_to_u32(smem);
    const int tid = threadIdx.x;
    const int lane = tid & 31;
    const int wid  = tid >> 5;
    const int warpM = wid >> 2;            // 0..1  (64 rows each)
    const int warpN = wid & 3;             // 0..3  (32 cols each)
    const int colBase = blockIdx.x * 128;
    const int rowBase = blockIdx.y * 128;

    // ---- A load mapping: 4 x 16B fp32 chunks per thread per k-block
    const int am = tid >> 3;               // 0..31 (+32*i)
    const int ac = (tid & 7) * 4;          // k offset (floats)
    const float* aPtr0 = A + (size_t)(rowBase + am) * DD + ac;
    const uint32_t aOff0 = am * 80 + ac * 2;
    const float* grow = SC ? (g + (size_t)(blockIdx.y >> 4) * DD + ac) : (const float*)0;

    // ---- B cp.async mapping: 2 x 16B chunks per ver per thread per k-block
    const int bn = tid >> 1;                    // 0..127
    const int bco = (tid & 1) * 32;             // byte offset of first chunk
    const size_t bSrc = (size_t)(colBase + bn) * DD + (bco >> 1);
    const uint32_t bDst = bn * 80 + bco;

    // ---- prologue: kb = 0
    float4 rA[4];
    float4 gs;
    #pragma unroll
    for (int i = 0; i < 4; i++)
        rA[i] = *(const float4*)(aPtr0 + (size_t)(32 * i) * DD);
    if (SC) gs = *(const float4*)(grow);
    cp16(sb + 20480 + bDst,      Bhi + bSrc);
    cp16(sb + 20480 + bDst + 16, Bhi + bSrc + 8);
    cp16(sb + 30720 + bDst,      Blo + bSrc);
    cp16(sb + 30720 + bDst + 16, Blo + bSrc + 8);
    CP_COMMIT();

    float acc[4][4][4];
    #pragma unroll
    for (int mf = 0; mf < 4; mf++)
        #pragma unroll
        for (int nf = 0; nf < 4; nf++)
            #pragma unroll
            for (int q = 0; q < 4; q++) acc[mf][nf][q] = 0.f;

    const int lrow = lane & 15;
    const int lc16 = (lane >> 4) * 16;
    const uint32_t aLdBase = (warpM * 64 + lrow) * 80 + lc16;
    const uint32_t bLdBase = 20480 + (warpN * 32 + lrow) * 80 + lc16;

    for (int kb = 0; kb < KB; kb++) {
        const int stOff = (kb & 1) * STAGE_B;
        const uint32_t st = sb + stOff;

        // store A (convert fp32 -> hi/lo bf16) for this kb
        #pragma unroll
        for (int i = 0; i < 4; i++) {
            float4 v = rA[i];
            if (SC) { v.x *= gs.x; v.y *= gs.y; v.z *= gs.z; v.w *= gs.w; }
            uint2 h = make_uint2(pack_hi(v.x, v.y), pack_hi(v.z, v.w));
            uint2 l = make_uint2(pack_lo(v.x, v.y), pack_lo(v.z, v.w));
            *(uint2*)(smem + stOff + aOff0 + i * (32 * 80))         = h;
            *(uint2*)(smem + stOff + aOff0 + i * (32 * 80) + 10240) = l;
        }

        if (kb + 1 < KB) {
            const int ko = (kb + 1) * 32;
            #pragma unroll
            for (int i = 0; i < 4; i++)
                rA[i] = *(const float4*)(aPtr0 + (size_t)(32 * i) * DD + ko);
            if (SC) gs = *(const float4*)(grow + ko);
            const uint32_t st2 = sb + ((kb + 1) & 1) * STAGE_B;
            cp16(st2 + 20480 + bDst,      Bhi + bSrc + ko);
            cp16(st2 + 20480 + bDst + 16, Bhi + bSrc + ko + 8);
            cp16(st2 + 30720 + bDst,      Blo + bSrc + ko);
            cp16(st2 + 30720 + bDst + 16, Blo + bSrc + ko + 8);
            CP_COMMIT();
            CP_WAIT_1();
        } else {
            CP_WAIT_0();
        }
        __syncthreads();

        // ---- compute on stage st (register-lean ordering)
        #pragma unroll
        for (int ks = 0; ks < 2; ks++) {
            uint32_t b0[4][2], b1[4][2];
            {
                const uint32_t bB = st + bLdBase + ks * 32;
                #pragma unroll
                for (int np = 0; np < 2; np++) {
                    uint32_t r[4];
                    LDSM4(r, bB + np * 16 * 80);            // B_hi
                    b0[np * 2 + 0][0] = r[0]; b0[np * 2 + 0][1] = r[2];
                    b0[np * 2 + 1][0] = r[1]; b0[np * 2 + 1][1] = r[3];
                }
                #pragma unroll
                for (int np = 0; np < 2; np++) {
                    uint32_t r[4];
                    LDSM4(r, bB + 10240 + np * 16 * 80);    // B_lo
                    b1[np * 2 + 0][0] = r[0]; b1[np * 2 + 0][1] = r[2];
                    b1[np * 2 + 1][0] = r[1]; b1[np * 2 + 1][1] = r[3];
                }
            }
            uint32_t a[4][4];
            const uint32_t aB = st + aLdBase + ks * 32;
            #pragma unroll
            for (int mf = 0; mf < 4; mf++)
                LDSM4(a[mf], aB + mf * 16 * 80);            // A_hi
            #pragma unroll
            for (int mf = 0; mf < 4; mf++)
                #pragma unroll
                for (int nf = 0; nf < 4; nf++) {
                    MMA_BF16(acc[mf][nf], a[mf], b0[nf]);   // Ahi*Bhi
                    MMA_BF16(acc[mf][nf], a[mf], b1[nf]);   // Ahi*Blo
                }
            #pragma unroll
            for (int mf = 0; mf < 4; mf++)
                LDSM4(a[mf], aB + 10240 + mf * 16 * 80);    // A_lo (reuse regs)
            #pragma unroll
            for (int mf = 0; mf < 4; mf++)
                #pragma unroll
                for (int nf = 0; nf < 4; nf++)
                    MMA_BF16(acc[mf][nf], a[mf], b0[nf]);   // Alo*Bhi
        }
        __syncthreads();
    }

    // ---- epilogue
    const int er = lane >> 2;
    const int ec = (lane & 3) * 2;
    #pragma unroll
    for (int mf = 0; mf < 4; mf++) {
        const int row0 = rowBase + warpM * 64 + mf * 16 + er;
        #pragma unroll
        for (int nf = 0; nf < 4; nf++) {
            const int col = colBase + warpN * 32 + nf * 8 + ec;
            float2 v0 = make_float2(acc[mf][nf][0], acc[mf][nf][1]);
            float2 v1 = make_float2(acc[mf][nf][2], acc[mf][nf][3]);
            if (RES) {
                const float2 r0 = *(const float2*)(res + (size_t)row0 * DD + col);
                const float2 r1 = *(const float2*)(res + (size_t)(row0 + 8) * DD + col);
                v0.x += r0.x; v0.y += r0.y; v1.x += r1.x; v1.y += r1.y;
            }
            *(float2*)(C + (size_t)row0 * DD + col) = v0;
            *(float2*)(C + (size_t)(row0 + 8) * DD + col) = v1;
        }
    }
}

// ======================= weight transpose + split ===========================
__global__ __launch_bounds__(256) void wsplit_kernel(
    const float* __restrict__ W, __nv_bfloat16* __restrict__ bhi,
    __nv_bfloat16* __restrict__ blo)
{
    __shared__ float tile[32][33];
    const int tx = threadIdx.x & 31, ty0 = threadIdx.x >> 5;
    const int nbase = blockIdx.x * 32, kbase = blockIdx.y * 32;
    #pragma unroll
    for (int j = 0; j < 4; j++) {
        int r = ty0 + j * 8;
        tile[r][tx] = W[(size_t)(kbase + r) * DD + nbase + tx];
    }
    __syncthreads();
    #pragma unroll
    for (int j = 0; j < 4; j++) {
        int n = nbase + ty0 + j * 8;
        int k = kbase + tx;
        float v = tile[tx][ty0 + j * 8];
        __nv_bfloat16 h = __float2bfloat16(v);
        float r = v - __bfloat162float(h);
        bhi[(size_t)n * DD + k] = h;
        blo[(size_t)n * DD + k] = __float2bfloat16(r);
    }
}

// ======================= middle kernels =====================================
__global__ __launch_bounds__(256) void logits_kernel(
    const float* __restrict__ X, const float* __restrict__ W,
    const float* __restrict__ mask, float* __restrict__ logits)
{
    const int m = blockIdx.x;
    const int b = m >> 11;
    const int s = m & (SS - 1);
    const int tid = threadIdx.x;
    const int h = tid >> 4, g = tid & 15;
    const float* xrow = X + (size_t)m * DD;

    float acc = 0.f;
    #pragma unroll 4
    for (int d = g; d < DD; d += 16)
        acc += xrow[d] * W[d * HH + h];

    __shared__ float red[256];
    red[tid] = acc;
    __syncthreads();
    if (tid < HH) {
        float v = 0.f;
        #pragma unroll
        for (int g2 = 0; g2 < 16; g2++) v += red[tid * 16 + g2];
        logits[((size_t)(b * HH + tid)) * SS + s] =
            v * 0.125f - (1.f - mask[m]) * 1e8f;
    }
}

// fused k logits: row s' of QK_flat = gather of K scaled by gq.
//   h' = s'>>7,  QK_flat[b,s',j*64+dh] = K[b, (s'&127)*16+j, h'*64+dh]*gq[b,h',dh]
__global__ __launch_bounds__(256) void k_logits_kernel(
    const float* __restrict__ K, const float* __restrict__ gq,
    const float* __restrict__ W, const float* __restrict__ mask,
    float* __restrict__ logits)
{
    const int m = blockIdx.x;
    const int b = m >> 11;
    const int s = m & (SS - 1);
    const int hp = s >> 7;
    const int sbase = (s & 127) * 16;
    const int tid = threadIdx.x;

    __shared__ float x[DD];
    __shared__ float red[256];

    const float* gqr = gq + (size_t)(b * HH + hp) * DHH;
    #pragma unroll
    for (int t = 0; t < 4; t++) {
        const int idx = tid + t * 256;
        const int j = idx >> 6, dh = idx & 63;
        x[idx] = K[((size_t)(b * SS + sbase + j)) * DD + hp * DHH + dh] * gqr[dh];
    }
    __syncthreads();

    const int h = tid >> 4, g = tid & 15;
    float acc = 0.f;
    #pragma unroll 4
    for (int d = g; d < DD; d += 16)
        acc += x[d] * W[d * HH + h];

    red[tid] = acc;
    __syncthreads();
    if (tid < HH) {
        float v = 0.f;
        #pragma unroll
        for (int g2 = 0; g2 < 16; g2++) v += red[tid * 16 + g2];
        logits[((size_t)(b * HH + tid)) * SS + s] =
            v * 0.125f - (1.f - mask[m]) * 1e8f;
    }
}

// att = softmax(logits[b,h,:]); gout[b,h,dh] = (gmul?) * sum_s att[s]*src[...]
template<bool GM>
__global__ __launch_bounds__(256) void softmax_wsum_kernel(
    const float* __restrict__ logits, const float* __restrict__ src,
    float* __restrict__ gout, const float* __restrict__ gmul)
{
    const int b = blockIdx.x >> 4, h = blockIdx.x & 15;
    const int tid = threadIdx.x;
    const float* lrow = logits + (size_t)(b * HH + h) * SS;

    __shared__ float att[SS];
    __shared__ float red[256];

    float mx = -3.4e38f;
    for (int s = tid; s < SS; s += 256) mx = fmaxf(mx, lrow[s]);
    red[tid] = mx; __syncthreads();
    for (int off = 128; off > 0; off >>= 1) {
        if (tid < off) red[tid] = fmaxf(red[tid], red[tid + off]);
        __syncthreads();
    }
    mx = red[0];
    __syncthreads();

    float sum = 0.f;
    for (int s = tid; s < SS; s += 256) {
        float e = expf(lrow[s] - mx);
        att[s] = e;
        sum += e;
    }
    red[tid] = sum; __syncthreads();
    for (int off = 128; off > 0; off >>= 1) {
        if (tid < off) red[tid] += red[tid + off];
        __syncthreads();
    }
    const float inv = 1.f / red[0];
    __syncthreads();

    const int dh = tid & 63, j = tid >> 6;
    const float* base = src + (size_t)b * (SS * DD) + h * DHH + dh;
    float acc = 0.f;
    for (int s = j; s < SS; s += 4)
        acc += att[s] * base[(size_t)s * DD];

    red[tid] = acc; __syncthreads();
    if (j == 0) {
        acc = red[dh] + red[64 + dh] + red[128 + dh] + red[192 + dh];
        float r = acc * inv;
        if (GM) r *= gmul[(b * HH + h) * DHH + dh];
        gout[(b * HH + h) * DHH + dh] = r;
    }
}

// ===========================================================================
extern "C" void kernel_launch(void* const* d_in, const int* in_sizes, int n_in,
                              void* d_out, int out_size)
{
    const float* Qseq  = (const float*)d_in[0];
    const float* Kseq  = (const float*)d_in[1];
    const float* Qmask = (const float*)d_in[2];
    const float* Kmask = (const float*)d_in[3];
    const float* WQ    = (const float*)d_in[4];
    const float* WK    = (const float*)d_in[5];
    const float* Wq    = (const float*)d_in[6];
    const float* Wk    = (const float*)d_in[7];
    const float* WP    = (const float*)d_in[8];
    float* out = (float*)d_out;

    float *pQ, *pK, *pL, *pgq, *pgk;
    __nv_bfloat16 *pBhi, *pBlo;
    cudaGetSymbolAddress((void**)&pQ,   g_Q);
    cudaGetSymbolAddress((void**)&pK,   g_K);
    cudaGetSymbolAddress((void**)&pL,   g_logits);
    cudaGetSymbolAddress((void**)&pgq,  g_gq);
    cudaGetSymbolAddress((void**)&pgk,  g_gk);
    cudaGetSymbolAddress((void**)&pBhi, g_Bhi);
    cudaGetSymbolAddress((void**)&pBlo, g_Blo);

    cudaFuncSetAttribute(hmma_gemm_kernel<false, false>,
                         cudaFuncAttributeMaxDynamicSharedMemorySize, GEMM_SMEM);
    cudaFuncSetAttribute(hmma_gemm_kernel<true, true>,
                         cudaFuncAttributeMaxDynamicSharedMemorySize, GEMM_SMEM);

    const dim3 gg(DD / 128, MM / 128);   // (8, 128)
    const dim3 wg(DD / 32, DD / 32);     // (32, 32)

    // 1) Q = Q_seq @ WQ
    wsplit_kernel<<<wg, 256>>>(WQ, pBhi, pBlo);
    hmma_gemm_kernel<false, false><<<gg, 256, GEMM_SMEM>>>(
        Qseq, pBhi, pBlo, pQ, nullptr, nullptr);

    // 2) K = K_seq @ WK
    wsplit_kernel<<<wg, 256>>>(WK, pBhi, pBlo);
    hmma_gemm_kernel<false, false><<<gg, 256, GEMM_SMEM>>>(
        Kseq, pBhi, pBlo, pK, nullptr, nullptr);

    // 3) q logits + softmax + global_q
    logits_kernel<<<MM, 256>>>(pQ, Wq, Qmask, pL);
    softmax_wsum_kernel<false><<<BB * HH, 256>>>(pL, pQ, pgq, nullptr);

    // 4) k logits (fused QK gather) + softmax + global_k (fused gq mul)
    k_logits_kernel<<<MM, 256>>>(pK, pgq, Wk, Kmask, pL);
    softmax_wsum_kernel<true><<<BB * HH, 256>>>(pL, pK, pgk, pgq);

    // 5) out = ((gk ⊙ Q) @ WP) + Q
    wsplit_kernel<<<wg, 256>>>(WP, pBhi, pBlo);
    hmma_gemm_kernel<true, true><<<gg, 256, GEMM_SMEM>>>(
        pQ, pBhi, pBlo, out, pgk, pQ);
}